// round 17
// baseline (speedup 1.0000x reference)
#include <cuda_runtime.h>

#define Bv 8
#define Sv 100
#define Tv 1200
#define NMELv 80
#define DMv 128
#define KKv 9

typedef unsigned long long u64;

// Scratch (no cudaMalloc allowed)
__device__ float g_x[Bv * Tv * NMELv];          // conv output
__device__ float g_xg[Bv * Tv * 768];           // GRU input projections
__device__ int   g_start[Bv * Sv];              // segment starts (prefix sums)
__device__ int   g_sorted[Bv * Sv];             // chain ids sorted by duration desc
__device__ int   g_ctr[2];                      // steal counters (per dir)

__device__ __forceinline__ float sigmoidf_fast(float x) {
    return __fdividef(1.f, 1.f + __expf(-x));
}
__device__ __forceinline__ float tanhf_fast(float x) {
    return 1.f - __fdividef(2.f, __expf(2.f * x) + 1.f);
}

// ---- packed f32x2 helpers (Blackwell sm_103a) ----
__device__ __forceinline__ u64 pk2(float lo, float hi) {
    u64 r; asm("mov.b64 %0, {%1, %2};" : "=l"(r) : "f"(lo), "f"(hi)); return r;
}
__device__ __forceinline__ void up2(u64 v, float& lo, float& hi) {
    asm("mov.b64 {%0, %1}, %2;" : "=f"(lo), "=f"(hi) : "l"(v));
}
__device__ __forceinline__ u64 fma2(u64 a, u64 b, u64 c) {
    u64 d; asm("fma.rn.f32x2 %0, %1, %2, %3;" : "=l"(d) : "l"(a), "l"(b), "l"(c)); return d;
}
__device__ __forceinline__ u64 add2(u64 a, u64 b) {
    u64 d; asm("add.rn.f32x2 %0, %1, %2;" : "=l"(d) : "l"(a), "l"(b)); return d;
}

#define PSW 134   // conv partial-row stride in u64 (1072 B, 16B-aligned rows)
#define PWW 130   // proj packed-W row stride in u64 (1040 B, 16B-aligned rows)
#define PXW 68    // proj X row stride in floats (272 B, 16B-aligned rows)
#define GWS 136   // gru W row stride (floats); kh offset 68 -> conflict-free LDS.128
#define HCS 136   // gru h chain stride (floats); kh read offset 72 -> disjoint banks

#define NITEMS_T 200   // 4-chain items (800 sorted chains / 4)
#define NSTATIC  74    // first item per block is static (rblk); rest stolen

// ---------------------------------------------------------------------------
// Kernel 1: fused conv stack (round-5 body, 49.6us) + prep fold-in block.
// ---------------------------------------------------------------------------
__global__ __launch_bounds__(128, 4) void conv_kernel(
    const float* __restrict__ mel, const int* __restrict__ mel_len,
    const int* __restrict__ durations,
    const float* __restrict__ w1, const float* __restrict__ g1, const float* __restrict__ be1,
    const float* __restrict__ w2, const float* __restrict__ g2, const float* __restrict__ be2)
{
    int bt = blockIdx.x;
    int c = threadIdx.x;

    // ---- prep block: scans, LPT sort, counter reset ----
    if (bt == Bv * Tv) {
        __shared__ int bcnt[9], boff[9];
        if (c < 2) g_ctr[c] = NSTATIC;
        if (c < 9) bcnt[c] = 0;
        int wid = c >> 5, lane = c & 31;
        if (wid < 4) {
            for (int rr = 2 * wid; rr < 2 * wid + 2; rr++) {
                int carry = 0;
                #pragma unroll
                for (int c0 = 0; c0 < 128; c0 += 32) {
                    int ss = c0 + lane;
                    int d = (ss < Sv) ? durations[rr * Sv + ss] : 0;
                    int v = d;
                    #pragma unroll
                    for (int off = 1; off < 32; off <<= 1) {
                        int n = __shfl_up_sync(0xFFFFFFFFu, v, off);
                        if (lane >= off) v += n;
                    }
                    if (ss < Sv) g_start[rr * Sv + ss] = carry + v - d;
                    carry += __shfl_sync(0xFFFFFFFFu, v, 31);
                }
            }
        }
        __syncthreads();
        for (int i = c; i < Bv * Sv; i += 128)
            atomicAdd(&bcnt[12 - durations[i]], 1);
        __syncthreads();
        if (c == 0) {
            int off = 0;
            for (int q = 0; q < 9; q++) { boff[q] = off; off += bcnt[q]; }
        }
        __syncthreads();
        for (int i = c; i < Bv * Sv; i += 128) {
            int pos = atomicAdd(&boff[12 - durations[i]], 1);
            g_sorted[pos] = i;
        }
        return;
    }

    int b = bt / Tv, t = bt - b * Tv;
    if (t >= mel_len[b]) return;

    extern __shared__ __align__(16) float sm[];
    u64* ps2 = (u64*)sm;                   // [40][PSW] packed partials
    u64* mp2 = ps2 + 40 * PSW;             // 48 packed mel pairs

    if (c < 48) {
        float lo = (c >= 4) ? mel[bt * NMELv + c - 4] : 0.f;
        float hi = (c < 44) ? mel[bt * NMELv + c + 36] : 0.f;
        mp2[c] = pk2(lo, hi);
    }

    float sc1c = g1[c] * rsqrtf(1.f + 1e-5f);
    float bb1c = be1[c];
    float s2   = g2[0] * rsqrtf(1.f + 1e-5f);
    u64 w1p[KKv], w2p[KKv];
    #pragma unroll
    for (int k = 0; k < KKv; k++) {
        float a = w1[c * KKv + k] * sc1c;  w1p[k] = pk2(a, a);
        float d = w2[c * KKv + k] * s2;    w2p[k] = pk2(d, d);
    }
    u64 bbp = pk2(bb1c, bb1c);
    __syncthreads();

    u64 Yp[48];
    u64 ring[9];
    #pragma unroll
    for (int j = 0; j < 8; j++) ring[j] = mp2[j];
    #pragma unroll
    for (int m = 0; m < 40; m++) {
        ring[(m + 8) % 9] = mp2[m + 8];
        u64 acc = bbp;
        #pragma unroll
        for (int k = 0; k < KKv; k++) acc = fma2(w1p[k], ring[(m + k) % 9], acc);
        float a, h; up2(acc, a, h);
        Yp[m + 4] = pk2(fmaxf(a, 0.f), fmaxf(h, 0.f));
    }
    #pragma unroll
    for (int j = 0; j < 4; j++) {
        float a, h;
        up2(Yp[40 + j], a, h); Yp[j]      = pk2(0.f, a);
        up2(Yp[4 + j],  a, h); Yp[44 + j] = pk2(h, 0.f);
    }

    #pragma unroll
    for (int m = 0; m < 40; m++) {
        u64 acc = 0ull;
        #pragma unroll
        for (int k = 0; k < KKv; k++) acc = fma2(w2p[k], Yp[m + k], acc);
        ps2[m * PSW + c] = acc;
    }
    __syncthreads();

    if (c < 40) {
        const ulonglong2* row = (const ulonglong2*)(ps2 + c * PSW);
        u64 s0 = 0ull, s1 = 0ull;
        #pragma unroll
        for (int q = 0; q < 32; q++) {
            ulonglong2 v0 = row[2 * q];
            ulonglong2 v1 = row[2 * q + 1];
            s0 = add2(s0, add2(v0.x, v0.y));
            s1 = add2(s1, add2(v1.x, v1.y));
        }
        u64 tot = add2(s0, s1);
        float a, h; up2(tot, a, h);
        float bb2 = be2[0];
        g_x[bt * NMELv + c]      = fmaxf(a + bb2, 0.f);
        g_x[bt * NMELv + c + 40] = fmaxf(h + bb2, 0.f);
    }
}

// ---------------------------------------------------------------------------
// Kernel 2: input projection GEMM (round-16 version, unchanged).
// ---------------------------------------------------------------------------
__global__ __launch_bounds__(256) void proj_kernel(
    const int* __restrict__ mel_len,
    const float* __restrict__ w_ih_f, const float* __restrict__ b_ih_f,
    const float* __restrict__ w_ih_b, const float* __restrict__ b_ih_b)
{
    int tid = threadIdx.x;
    int b   = blockIdx.z;
    int f0l = blockIdx.x * 64;
    int g0  = blockIdx.y * 128;

    if (f0l >= mel_len[b]) return;

    extern __shared__ __align__(16) char smc[];
    u64*   Ws2 = (u64*)smc;                  // [80][PWW] duplicated pairs
    float* Xs  = (float*)(Ws2 + 80 * PWW);   // [80][PXW]

    for (int i = tid; i < 64 * NMELv; i += 256) {
        int r = i / NMELv, m = i - r * NMELv;
        int fr = min(f0l + r, Tv - 1);
        Xs[m * PXW + r] = g_x[(b * Tv + fr) * NMELv + m];
    }
    const float* wsrc = (g0 < 384) ? (w_ih_f + g0 * NMELv) : (w_ih_b + (g0 - 384) * NMELv);
    const float* bsrc = (g0 < 384) ? (b_ih_f + g0) : (b_ih_b + (g0 - 384));
    for (int i = tid; i < 128 * NMELv; i += 256) {
        int cc = i / NMELv, m = i - cc * NMELv;
        float v = wsrc[i];
        Ws2[m * PWW + cc] = pk2(v, v);
    }
    __syncthreads();

    int tx = tid & 15, ty = tid >> 4;
    u64 acc[8][2];
    #pragma unroll
    for (int u = 0; u < 8; u++) { acc[u][0] = 0ull; acc[u][1] = 0ull; }

    #pragma unroll 4
    for (int m = 0; m < NMELv; m++) {
        ulonglong2 xp = *(const ulonglong2*)&Xs[m * PXW + ty * 4];
        #pragma unroll
        for (int u = 0; u < 8; u++) {
            u64 wp = Ws2[m * PWW + tx + 16 * u];
            acc[u][0] = fma2(wp, xp.x, acc[u][0]);
            acc[u][1] = fma2(wp, xp.y, acc[u][1]);
        }
    }
    #pragma unroll
    for (int u = 0; u < 8; u++) {
        int cc = tx + 16 * u;
        float bias = bsrc[cc];
        float a[4];
        up2(acc[u][0], a[0], a[1]);
        up2(acc[u][1], a[2], a[3]);
        #pragma unroll
        for (int v = 0; v < 4; v++) {
            int rr = ty * 4 + v;
            if (f0l + rr < Tv)
                g_xg[(b * Tv + f0l + rr) * 768 + g0 + cc] = a[v] + bias;
        }
    }
}

// ---------------------------------------------------------------------------
// Kernel 3: segment GRU v13 — v10 dataflow, k-split across 8 warps on ONE item.
// lane pairing: kh = lane&1 (k-half), g = warp*16 + lane/2 (hidden unit).
// W stride GWS=136, kh offset 68 (conflict-free LDS.128); h stride HCS=136
// with kh read offset 72 (disjoint bank groups). shfl.xor(1) combines halves.
// 148 blocks (dir = bid&1), static first item + stealing. 1 barrier/step.
// ---------------------------------------------------------------------------
__global__ void __launch_bounds__(256, 1) gru_kernel(
    const int* __restrict__ durations, const int* __restrict__ src_len,
    const float* __restrict__ w_hh_f, const float* __restrict__ b_hh_f,
    const float* __restrict__ w_hh_b, const float* __restrict__ b_hh_b,
    float* __restrict__ out)
{
    int dir = blockIdx.x & 1;
    int rblk = blockIdx.x >> 1;        // 0..73 per dir
    int tid = threadIdx.x;
    int lane = tid & 31, warp = tid >> 5;
    int g = (warp << 4) | (lane >> 1); // hidden unit 0..127
    int kh = lane & 1;                 // k-half

    extern __shared__ __align__(16) float smg[];
    float* Wt = smg;                       // [384][GWS], halves at +0 / +68
    float* hb = Wt + 384 * GWS;            // [2 buf][4 chains][HCS]
    int* itemS = (int*)(hb + 2 * 4 * HCS);

    // Load W once: floats [0..63] -> +0, [64..127] -> +68 within each row
    const float* whh = dir ? w_hh_b : w_hh_f;
    {
        const float4* src = (const float4*)whh;
        for (int i = tid; i < 384 * 32; i += 256) {
            int row = i >> 5, q = i & 31;
            int dst = row * GWS + ((q < 16) ? 4 * q : 4 * q + 4);
            *(float4*)&Wt[dst] = src[i];
        }
    }
    __syncthreads();

    const float* bhh = dir ? b_hh_b : b_hh_f;
    float br = bhh[g], bz = bhh[128 + g], bn = bhh[256 + g];
    int kq = 68 * kh;
    const float* wr = Wt + g * GWS + kq;
    const float* wz = Wt + (128 + g) * GWS + kq;
    const float* wn = Wt + (256 + g) * GWS + kq;
    const float* xbase = g_xg + dir * 384;
    int hof = 72 * kh;                  // h read offset for this k-half
    int gpos = g + ((g >> 6) << 3);     // h write position (gap of 8 at k=64)

    int item = rblk;
    while (item < NITEMS_T) {
        int ee[4], st[4], du[4], bt4[4];
        #pragma unroll
        for (int cb = 0; cb < 4; cb++) {
            int e = g_sorted[item * 4 + cb];
            ee[cb] = e;
            st[cb] = g_start[e];
            du[cb] = durations[e];
            bt4[cb] = (e / Sv) * Tv;
        }
        int maxd = du[0];               // globally sorted desc -> first is max

        float hold[4] = {0.f, 0.f, 0.f, 0.f};
        for (int j = tid; j < 4 * HCS; j += 256) hb[j] = 0.f;   // buffer 0
        __syncthreads();

        for (int i = 0; i < maxd; i++) {
            const float* hcur = hb + (i & 1) * (4 * HCS);
            float* hnxt = hb + ((i + 1) & 1) * (4 * HCS);

            float xr[4], xz[4], xn4[4];
            #pragma unroll
            for (int cb = 0; cb < 4; cb++) {
                int d = du[cb];
                int ie = min(i, d - 1);
                int t = st[cb] + (dir ? (d - 1 - ie) : ie);
                const float* p = xbase + (bt4[cb] + t) * 768;
                xr[cb] = p[g]; xz[cb] = p[128 + g]; xn4[cb] = p[256 + g];
            }

            u64 ar[4], az[4], an[4];
            #pragma unroll
            for (int cb = 0; cb < 4; cb++) { ar[cb] = 0ull; az[cb] = 0ull; an[cb] = 0ull; }

            #pragma unroll 4
            for (int j4 = 0; j4 < 16; j4++) {
                ulonglong2 wrp = *(const ulonglong2*)(wr + 4 * j4);
                ulonglong2 wzp = *(const ulonglong2*)(wz + 4 * j4);
                ulonglong2 wnp = *(const ulonglong2*)(wn + 4 * j4);
                #pragma unroll
                for (int cb = 0; cb < 4; cb++) {
                    ulonglong2 hp = *(const ulonglong2*)(hcur + cb * HCS + hof + 4 * j4);
                    ar[cb] = fma2(wrp.x, hp.x, ar[cb]);
                    ar[cb] = fma2(wrp.y, hp.y, ar[cb]);
                    az[cb] = fma2(wzp.x, hp.x, az[cb]);
                    az[cb] = fma2(wzp.y, hp.y, az[cb]);
                    an[cb] = fma2(wnp.x, hp.x, an[cb]);
                    an[cb] = fma2(wnp.y, hp.y, an[cb]);
                }
            }

            // combine k-halves (lane pairs) and run identical epilogues
            #pragma unroll
            for (int cb = 0; cb < 4; cb++) {
                u64 art = add2(ar[cb], __shfl_xor_sync(0xFFFFFFFFu, ar[cb], 1));
                u64 azt = add2(az[cb], __shfl_xor_sync(0xFFFFFFFFu, az[cb], 1));
                u64 ant = add2(an[cb], __shfl_xor_sync(0xFFFFFFFFu, an[cb], 1));
                float e0, e1;
                up2(art, e0, e1);
                float rr = sigmoidf_fast(xr[cb] + br + e0 + e1);
                up2(azt, e0, e1);
                float zz = sigmoidf_fast(xz[cb] + bz + e0 + e1);
                up2(ant, e0, e1);
                float nv = tanhf_fast(fmaf(rr, bn + e0 + e1, xn4[cb]));
                float hv = fmaf(zz, hold[cb] - nv, nv);     // (1-z)*n + z*h
                if (i < du[cb]) hold[cb] = hv;              // freeze after segment end
                if (kh == 0) hnxt[cb * HCS + gpos] = hold[cb];
            }
            __syncthreads();            // ONE barrier per step
        }

        if (kh == 0) {
            #pragma unroll
            for (int cb = 0; cb < 4; cb++) {
                int e = ee[cb];
                int bb = e / Sv, ss = e - bb * Sv;
                float v = (ss < src_len[bb]) ? hold[cb] : 0.f;
                out[e * 256 + dir * 128 + g] = v;
            }
        }

        __syncthreads();
        if (tid == 0) itemS[0] = atomicAdd(&g_ctr[dir], 1);
        __syncthreads();
        item = itemS[0];
    }
}

// ---------------------------------------------------------------------------
extern "C" void kernel_launch(void* const* d_in, const int* in_sizes, int n_in,
                              void* d_out, int out_size) {
    const float* mel      = (const float*)d_in[0];
    const int*   durations= (const int*)d_in[1];
    const int*   mel_len  = (const int*)d_in[2];
    const int*   src_len  = (const int*)d_in[3];
    const float* w1       = (const float*)d_in[4];
    const float* g1       = (const float*)d_in[5];
    const float* be1      = (const float*)d_in[6];
    const float* w2       = (const float*)d_in[7];
    const float* g2       = (const float*)d_in[8];
    const float* be2      = (const float*)d_in[9];
    const float* w_ih_f   = (const float*)d_in[10];
    const float* w_hh_f   = (const float*)d_in[11];
    const float* b_ih_f   = (const float*)d_in[12];
    const float* b_hh_f   = (const float*)d_in[13];
    const float* w_ih_b   = (const float*)d_in[14];
    const float* w_hh_b   = (const float*)d_in[15];
    const float* b_ih_b   = (const float*)d_in[16];
    const float* b_hh_b   = (const float*)d_in[17];
    float* out = (float*)d_out;

    size_t conv_smem = (size_t)(40 * PSW + 48) * sizeof(u64);
    size_t proj_smem = (size_t)(80 * PWW) * sizeof(u64) + (size_t)(80 * PXW) * sizeof(float);
    size_t gru_smem  = (size_t)(384 * GWS + 2 * 4 * HCS) * sizeof(float) + 16;
    cudaFuncSetAttribute(conv_kernel, cudaFuncAttributeMaxDynamicSharedMemorySize, (int)conv_smem);
    cudaFuncSetAttribute(proj_kernel, cudaFuncAttributeMaxDynamicSharedMemorySize, (int)proj_smem);
    cudaFuncSetAttribute(gru_kernel,  cudaFuncAttributeMaxDynamicSharedMemorySize, (int)gru_smem);

    conv_kernel<<<Bv * Tv + 1, 128, conv_smem>>>(mel, mel_len, durations,
                                                 w1, g1, be1, w2, g2, be2);
    proj_kernel<<<dim3(19, 6, 8), 256, proj_smem>>>(mel_len, w_ih_f, b_ih_f, w_ih_b, b_ih_b);
    gru_kernel<<<148, 256, gru_smem>>>(durations, src_len, w_hh_f, b_hh_f, w_hh_b, b_hh_b, out);
}